// round 10
// baseline (speedup 1.0000x reference)
#include <cuda_runtime.h>
#include <cstdint>

#define H 320
#define W 960
#define HW (H * W)
#define PAD 128   // slack so left-window vector loads can't run past the array

// Fused prep tile config
#define TX 64
#define TY 8
#define SX (TX + 4)
#define SY (TY + 4)

// Disparities per volume block (multiple of 8: keeps 32B alignment of left v8 loads)
#define DPB 8

// Scratch (allocation-free: __device__ globals). Y plane never hits global.
__device__ float g_cbL[HW + PAD], g_cbR[HW + PAD];
__device__ float g_crL[HW + PAD], g_crR[HW + PAD];
__device__ unsigned g_cL[HW + PAD], g_cR[HW + PAD];

// ---- Blackwell 256-bit global memory ops (LDG/STG.E.256) ----
__device__ __forceinline__ void ld256(const void* p, unsigned v[8]) {
    asm("ld.global.v8.b32 {%0,%1,%2,%3,%4,%5,%6,%7}, [%8];"
        : "=r"(v[0]), "=r"(v[1]), "=r"(v[2]), "=r"(v[3]),
          "=r"(v[4]), "=r"(v[5]), "=r"(v[6]), "=r"(v[7])
        : "l"(p));
}
__device__ __forceinline__ void st256_cs(void* p, const unsigned v[8]) {
    asm volatile("st.global.cs.v8.b32 [%0], {%1,%2,%3,%4,%5,%6,%7,%8};"
        :: "l"(p),
           "r"(v[0]), "r"(v[1]), "r"(v[2]), "r"(v[3]),
           "r"(v[4]), "r"(v[5]), "r"(v[6]), "r"(v[7])
        : "memory");
}

// Fused YCbCr + census. One block per 64x8 tile per image (blockIdx.z).
__global__ __launch_bounds__(256) void prep_kernel(const float* __restrict__ left,
                                                   const float* __restrict__ right) {
    int img = blockIdx.z;
    const float* src = img ? right : left;
    float* cb    = img ? g_cbR : g_cbL;
    float* cr    = img ? g_crR : g_crL;
    unsigned* C  = img ? g_cR  : g_cL;

    __shared__ float sY[SY][SX];
    int tx0 = blockIdx.x * TX, ty0 = blockIdx.y * TY;

    // Phase 1: compute Y for tile+halo into smem; write cb/cr for interior.
    for (int idx = threadIdx.x; idx < SX * SY; idx += 256) {
        int sy = idx / SX, sx = idx - sy * SX;
        int gx = tx0 + sx - 2, gy = ty0 + sy - 2;
        float yv = 0.0f;
        if (gx >= 0 && gx < W && gy >= 0 && gy < H) {
            int p = gy * W + gx;
            float r = src[p], g = src[HW + p], b = src[2 * HW + p];
            yv = 0.299f * r + 0.587f * g + 0.114f * b;
            if (sx >= 2 && sx < SX - 2 && sy >= 2 && sy < SY - 2) {
                cb[p] = (b - yv) * 0.564f + 0.5f;
                cr[p] = (r - yv) * 0.713f + 0.5f;
            }
        }
        sY[sy][sx] = yv;
    }
    __syncthreads();

    // Phase 2: census from smem.
    int px = threadIdx.x % TX;
    for (int py = threadIdx.x / TX; py < TY; py += 256 / TX) {
        int gx = tx0 + px, gy = ty0 + py;
        unsigned cen = 0u;
        if (gx >= 2 && gx < W - 2 && gy >= 2 && gy < H - 2) {
            float c = sY[py + 2][px + 2];
            #pragma unroll
            for (int v = 0; v < 5; v++) {
                #pragma unroll
                for (int u = 0; u < 5; u++) {
                    if (v == 1 && u == 1) continue;  // reference skips (1,1), NOT the center
                    cen = (cen << 1) | (sY[py + v][px + u] >= c ? 1u : 0u);
                }
            }
        }
        C[gy * W + gx] = cen;
    }
}

// One block per (d-group of DPB, y). 120 lanes each produce 8 consecutive x
// (one 256-bit store) for three channel groups across DPB disparities.
// All global traffic is 256-bit (v8): halves L1 wavefront + issue cost per
// byte vs v4, leaving DRAM write bandwidth as the sole limiter.
// Left windows are 32B-aligned because x%8==0 and d0%8==0.
__global__ __launch_bounds__(128) void volume_kernel(float* __restrict__ out,
                                                     int maxdisp) {
    int d0 = blockIdx.x * DPB;
    int y  = blockIdx.y;
    int lane = threadIdx.x;
    if (lane >= W / 8) return;
    int x = lane * 8;
    int rbase = y * W + x;

    unsigned cR[8];  ld256(&g_cR[rbase],  cR);
    unsigned cbRu[8]; ld256(&g_cbR[rbase], cbRu);
    unsigned crRu[8]; ld256(&g_crR[rbase], crRu);
    float cbR[8], crR[8];
    #pragma unroll
    for (int j = 0; j < 8; j++) { cbR[j] = __uint_as_float(cbRu[j]); crR[j] = __uint_as_float(crRu[j]); }

    // Left windows: DPB+8 = 16 words per array, 32B-aligned, two v8 loads each.
    int lb = rbase + d0;
    unsigned cl[16], blu[16], rlu[16];
    ld256(&g_cL[lb],      cl);      ld256(&g_cL[lb + 8],  cl + 8);
    ld256(&g_cbL[lb],     blu);     ld256(&g_cbL[lb + 8], blu + 8);
    ld256(&g_crL[lb],     rlu);     ld256(&g_crL[lb + 8], rlu + 8);
    float bl[16], rl[16];
    #pragma unroll
    for (int j = 0; j < 16; j++) { bl[j] = __uint_as_float(blu[j]); rl[j] = __uint_as_float(rlu[j]); }

    size_t stride = (size_t)maxdisp * HW;
    int rem = W - x - d0;   // element (dd, j) valid iff dd + j < rem

    #pragma unroll
    for (int dd = 0; dd < DPB; dd++) {
        int d = d0 + dd;

        unsigned ham[8], dcb[8], dcr[8];
        #pragma unroll
        for (int j = 0; j < 8; j++) {
            bool valid = (dd + j) < rem;
            ham[j] = valid ? __float_as_uint((float)__popc(cl[dd + j] ^ cR[j])) : 0u;
            dcb[j] = valid ? __float_as_uint(fabsf(bl[dd + j] - cbR[j])) : 0u;
            dcr[j] = valid ? __float_as_uint(fabsf(rl[dd + j] - crR[j])) : 0u;
        }

        size_t o = ((size_t)d * H + y) * W + x;
        st256_cs(&out[o],              ham);
        st256_cs(&out[o + stride],     dcb);
        st256_cs(&out[o + 2 * stride], dcr);
    }
}

extern "C" void kernel_launch(void* const* d_in, const int* in_sizes, int n_in,
                              void* d_out, int out_size) {
    const float* left  = (const float*)d_in[0];
    const float* right = (const float*)d_in[1];
    float* out = (float*)d_out;
    // maxdisp lives in device memory (d_in[2]); derive it host-side from out_size.
    int maxdisp = out_size / (3 * HW);   // = 128 for the bench shape

    dim3 pgrid(W / TX, H / TY, 2);       // 15 x 40 x 2
    prep_kernel<<<pgrid, 256>>>(left, right);

    dim3 vgrid((maxdisp + DPB - 1) / DPB, H);  // maxdisp=128 divisible by DPB=8
    volume_kernel<<<vgrid, 128>>>(out, maxdisp);
}

// round 13
// speedup vs baseline: 1.1057x; 1.1057x over previous
#include <cuda_runtime.h>
#include <cstdint>

#define H 320
#define W 960
#define HW (H * W)
#define PAD 128   // slack so left-window vector loads can't run past the array

// Fused prep tile config
#define TX 64
#define TY 8
#define SX (TX + 4)
#define SY (TY + 4)

// Disparities per volume block (multiple of 4 for aligned left loads)
#define DPB 8

// Scratch (allocation-free: __device__ globals). Y plane never hits global.
__device__ float g_cbL[HW + PAD], g_cbR[HW + PAD];
__device__ float g_crL[HW + PAD], g_crR[HW + PAD];
__device__ unsigned g_cL[HW + PAD], g_cR[HW + PAD];

// Fused YCbCr + census. One block per 64x8 tile per image (blockIdx.z).
__global__ __launch_bounds__(256) void prep_kernel(const float* __restrict__ left,
                                                   const float* __restrict__ right) {
    int img = blockIdx.z;
    const float* src = img ? right : left;
    float* cb    = img ? g_cbR : g_cbL;
    float* cr    = img ? g_crR : g_crL;
    unsigned* C  = img ? g_cR  : g_cL;

    __shared__ float sY[SY][SX];
    int tx0 = blockIdx.x * TX, ty0 = blockIdx.y * TY;

    // Phase 1: compute Y for tile+halo into smem; write cb/cr for interior.
    for (int idx = threadIdx.x; idx < SX * SY; idx += 256) {
        int sy = idx / SX, sx = idx - sy * SX;
        int gx = tx0 + sx - 2, gy = ty0 + sy - 2;
        float yv = 0.0f;
        if (gx >= 0 && gx < W && gy >= 0 && gy < H) {
            int p = gy * W + gx;
            float r = src[p], g = src[HW + p], b = src[2 * HW + p];
            yv = 0.299f * r + 0.587f * g + 0.114f * b;
            if (sx >= 2 && sx < SX - 2 && sy >= 2 && sy < SY - 2) {
                cb[p] = (b - yv) * 0.564f + 0.5f;
                cr[p] = (r - yv) * 0.713f + 0.5f;
            }
        }
        sY[sy][sx] = yv;
    }
    __syncthreads();

    // Phase 2: census from smem.
    int px = threadIdx.x % TX;
    for (int py = threadIdx.x / TX; py < TY; py += 256 / TX) {
        int gx = tx0 + px, gy = ty0 + py;
        unsigned cen = 0u;
        if (gx >= 2 && gx < W - 2 && gy >= 2 && gy < H - 2) {
            float c = sY[py + 2][px + 2];
            #pragma unroll
            for (int v = 0; v < 5; v++) {
                #pragma unroll
                for (int u = 0; u < 5; u++) {
                    if (v == 1 && u == 1) continue;  // reference skips (1,1), NOT the center
                    cen = (cen << 1) | (sY[py + v][px + u] >= c ? 1u : 0u);
                }
            }
        }
        C[gy * W + gx] = cen;
    }

    // PDL: allow the dependent volume kernel to begin launching.
    asm volatile("griddepcontrol.launch_dependents;");
}

// One block per (d-group of DPB, y). Lanes 0..239 produce 4 consecutive x for
// three channel groups (hamming, |dCb|, |dCr|) across DPB disparities.
// Left operands: d0 % 4 == 0 -> thread's left window over all DPB disparities
// is left[x+d0 .. x+d0+DPB+3] -> (DPB/4 + 1) ALIGNED vector loads per array;
// per-disparity selection is register shuffling (free under full unroll).
// Out-of-range lanes read neighbor-row garbage (masked on output; arrays padded).
__global__ __launch_bounds__(256) void volume_kernel(float* __restrict__ out,
                                                     int maxdisp) {
    int d0 = blockIdx.x * DPB;
    int y  = blockIdx.y;
    int lane = threadIdx.x;
    int x = lane * 4;
    int rbase = y * W + x;
    size_t stride = (size_t)maxdisp * HW;
    int rem = W - x - d0;   // element (dd, j) valid iff dd + j < rem

    // PDL: block until prep_kernel has fully completed (all its stores visible).
    asm volatile("griddepcontrol.wait;");

    if (lane >= W / 4) return;

    uint4  c4  = *reinterpret_cast<const uint4*>(&g_cR[rbase]);
    float4 cb4 = *reinterpret_cast<const float4*>(&g_cbR[rbase]);
    float4 cr4 = *reinterpret_cast<const float4*>(&g_crR[rbase]);
    unsigned cR[4] = {c4.x, c4.y, c4.z, c4.w};
    float cbR[4]   = {cb4.x, cb4.y, cb4.z, cb4.w};
    float crR[4]   = {cr4.x, cr4.y, cr4.z, cr4.w};

    // Left windows: DPB+4 = 12 words per array, 16B-aligned.
    int lb = rbase + d0;
    unsigned cl[DPB + 4];
    float    bl[DPB + 4];
    float    rl[DPB + 4];
    #pragma unroll
    for (int g = 0; g < (DPB + 4) / 4; g++) {
        uint4  cv = *reinterpret_cast<const uint4*>(&g_cL[lb + 4 * g]);
        float4 bv = *reinterpret_cast<const float4*>(&g_cbL[lb + 4 * g]);
        float4 rv = *reinterpret_cast<const float4*>(&g_crL[lb + 4 * g]);
        cl[4 * g + 0] = cv.x; cl[4 * g + 1] = cv.y; cl[4 * g + 2] = cv.z; cl[4 * g + 3] = cv.w;
        bl[4 * g + 0] = bv.x; bl[4 * g + 1] = bv.y; bl[4 * g + 2] = bv.z; bl[4 * g + 3] = bv.w;
        rl[4 * g + 0] = rv.x; rl[4 * g + 1] = rv.y; rl[4 * g + 2] = rv.z; rl[4 * g + 3] = rv.w;
    }

    #pragma unroll
    for (int dd = 0; dd < DPB; dd++) {
        int d = d0 + dd;

        float ham[4], dcb[4], dcr[4];
        #pragma unroll
        for (int j = 0; j < 4; j++) {
            bool valid = (dd + j) < rem;
            ham[j] = valid ? (float)__popc(cl[dd + j] ^ cR[j]) : 0.0f;
            dcb[j] = valid ? fabsf(bl[dd + j] - cbR[j]) : 0.0f;
            dcr[j] = valid ? fabsf(rl[dd + j] - crR[j]) : 0.0f;
        }

        size_t o = ((size_t)d * H + y) * W + x;
        __stcs(reinterpret_cast<float4*>(&out[o]),
               make_float4(ham[0], ham[1], ham[2], ham[3]));
        __stcs(reinterpret_cast<float4*>(&out[o + stride]),
               make_float4(dcb[0], dcb[1], dcb[2], dcb[3]));
        __stcs(reinterpret_cast<float4*>(&out[o + 2 * stride]),
               make_float4(dcr[0], dcr[1], dcr[2], dcr[3]));
    }
}

extern "C" void kernel_launch(void* const* d_in, const int* in_sizes, int n_in,
                              void* d_out, int out_size) {
    const float* left  = (const float*)d_in[0];
    const float* right = (const float*)d_in[1];
    float* out = (float*)d_out;
    // maxdisp lives in device memory (d_in[2]); derive it host-side from out_size.
    int maxdisp = out_size / (3 * HW);   // = 128 for the bench shape

    dim3 pgrid(W / TX, H / TY, 2);       // 15 x 40 x 2
    prep_kernel<<<pgrid, 256>>>(left, right);

    // Volume kernel launched with PDL so its launch/prologue overlaps prep's tail.
    cudaLaunchConfig_t cfg = {};
    cfg.gridDim  = dim3((maxdisp + DPB - 1) / DPB, H);  // 16 x 320
    cfg.blockDim = dim3(256, 1, 1);
    cfg.dynamicSmemBytes = 0;
    cfg.stream = 0;
    cudaLaunchAttribute attr[1];
    attr[0].id = cudaLaunchAttributeProgrammaticStreamSerialization;
    attr[0].val.programmaticStreamSerializationAllowed = 1;
    cfg.attrs = attr;
    cfg.numAttrs = 1;
    cudaLaunchKernelEx(&cfg, volume_kernel, out, maxdisp);
}

// round 14
// speedup vs baseline: 1.1356x; 1.0270x over previous
#include <cuda_runtime.h>
#include <cstdint>

#define H 320
#define W 960
#define HW (H * W)
#define PAD 128   // slack so left-window vector loads can't run past the array

// Fused prep tile config
#define TX 64
#define TY 8
#define SX (TX + 4)
#define SY (TY + 4)

// Disparities per volume block (multiple of 4 for aligned left loads)
#define DPB 8

// Scratch (allocation-free: __device__ globals). Y plane never hits global.
__device__ float g_cbL[HW + PAD], g_cbR[HW + PAD];
__device__ float g_crL[HW + PAD], g_crR[HW + PAD];
__device__ unsigned g_cL[HW + PAD], g_cR[HW + PAD];

// Fused YCbCr + census. One block per 64x8 tile per image (blockIdx.z).
__global__ __launch_bounds__(256) void prep_kernel(const float* __restrict__ left,
                                                   const float* __restrict__ right) {
    int img = blockIdx.z;
    const float* src = img ? right : left;
    float* cb    = img ? g_cbR : g_cbL;
    float* cr    = img ? g_crR : g_crL;
    unsigned* C  = img ? g_cR  : g_cL;

    __shared__ float sY[SY][SX];
    int tx0 = blockIdx.x * TX, ty0 = blockIdx.y * TY;

    // Phase 1: compute Y for tile+halo into smem; write cb/cr for interior.
    for (int idx = threadIdx.x; idx < SX * SY; idx += 256) {
        int sy = idx / SX, sx = idx - sy * SX;
        int gx = tx0 + sx - 2, gy = ty0 + sy - 2;
        float yv = 0.0f;
        if (gx >= 0 && gx < W && gy >= 0 && gy < H) {
            int p = gy * W + gx;
            float r = src[p], g = src[HW + p], b = src[2 * HW + p];
            yv = 0.299f * r + 0.587f * g + 0.114f * b;
            if (sx >= 2 && sx < SX - 2 && sy >= 2 && sy < SY - 2) {
                cb[p] = (b - yv) * 0.564f + 0.5f;
                cr[p] = (r - yv) * 0.713f + 0.5f;
            }
        }
        sY[sy][sx] = yv;
    }
    __syncthreads();

    // Phase 2: census from smem.
    int px = threadIdx.x % TX;
    for (int py = threadIdx.x / TX; py < TY; py += 256 / TX) {
        int gx = tx0 + px, gy = ty0 + py;
        unsigned cen = 0u;
        if (gx >= 2 && gx < W - 2 && gy >= 2 && gy < H - 2) {
            float c = sY[py + 2][px + 2];
            #pragma unroll
            for (int v = 0; v < 5; v++) {
                #pragma unroll
                for (int u = 0; u < 5; u++) {
                    if (v == 1 && u == 1) continue;  // reference skips (1,1), NOT the center
                    cen = (cen << 1) | (sY[py + v][px + u] >= c ? 1u : 0u);
                }
            }
        }
        C[gy * W + gx] = cen;
    }

    // PDL: allow the dependent volume kernel to begin launching.
    asm volatile("griddepcontrol.launch_dependents;");
}

// One block per (y, d-group). blockIdx.x = y (FASTEST): concurrent blocks
// share a d-group and write CONSECUTIVE y rows -> the chip-level store stream
// is ~24 long sequential regions instead of thousands of scattered 3.8KB rows
// (DRAM page/burst locality). Reads stay L2-resident regardless of order.
// Lanes 0..239 produce 4 consecutive x for three channel groups across DPB
// disparities; left windows are aligned vector loads (d0 % 4 == 0).
// Out-of-range lanes read neighbor-row garbage (masked on output; arrays padded).
__global__ __launch_bounds__(256) void volume_kernel(float* __restrict__ out,
                                                     int maxdisp) {
    int y  = blockIdx.x;
    int d0 = blockIdx.y * DPB;
    int lane = threadIdx.x;
    int x = lane * 4;
    int rbase = y * W + x;
    size_t stride = (size_t)maxdisp * HW;
    int rem = W - x - d0;   // element (dd, j) valid iff dd + j < rem

    // PDL: block until prep_kernel has fully completed (all its stores visible).
    asm volatile("griddepcontrol.wait;");

    if (lane >= W / 4) return;

    uint4  c4  = *reinterpret_cast<const uint4*>(&g_cR[rbase]);
    float4 cb4 = *reinterpret_cast<const float4*>(&g_cbR[rbase]);
    float4 cr4 = *reinterpret_cast<const float4*>(&g_crR[rbase]);
    unsigned cR[4] = {c4.x, c4.y, c4.z, c4.w};
    float cbR[4]   = {cb4.x, cb4.y, cb4.z, cb4.w};
    float crR[4]   = {cr4.x, cr4.y, cr4.z, cr4.w};

    // Left windows: DPB+4 = 12 words per array, 16B-aligned.
    int lb = rbase + d0;
    unsigned cl[DPB + 4];
    float    bl[DPB + 4];
    float    rl[DPB + 4];
    #pragma unroll
    for (int g = 0; g < (DPB + 4) / 4; g++) {
        uint4  cv = *reinterpret_cast<const uint4*>(&g_cL[lb + 4 * g]);
        float4 bv = *reinterpret_cast<const float4*>(&g_cbL[lb + 4 * g]);
        float4 rv = *reinterpret_cast<const float4*>(&g_crL[lb + 4 * g]);
        cl[4 * g + 0] = cv.x; cl[4 * g + 1] = cv.y; cl[4 * g + 2] = cv.z; cl[4 * g + 3] = cv.w;
        bl[4 * g + 0] = bv.x; bl[4 * g + 1] = bv.y; bl[4 * g + 2] = bv.z; bl[4 * g + 3] = bv.w;
        rl[4 * g + 0] = rv.x; rl[4 * g + 1] = rv.y; rl[4 * g + 2] = rv.z; rl[4 * g + 3] = rv.w;
    }

    #pragma unroll
    for (int dd = 0; dd < DPB; dd++) {
        int d = d0 + dd;

        float ham[4], dcb[4], dcr[4];
        #pragma unroll
        for (int j = 0; j < 4; j++) {
            bool valid = (dd + j) < rem;
            ham[j] = valid ? (float)__popc(cl[dd + j] ^ cR[j]) : 0.0f;
            dcb[j] = valid ? fabsf(bl[dd + j] - cbR[j]) : 0.0f;
            dcr[j] = valid ? fabsf(rl[dd + j] - crR[j]) : 0.0f;
        }

        size_t o = ((size_t)d * H + y) * W + x;
        __stcs(reinterpret_cast<float4*>(&out[o]),
               make_float4(ham[0], ham[1], ham[2], ham[3]));
        __stcs(reinterpret_cast<float4*>(&out[o + stride]),
               make_float4(dcb[0], dcb[1], dcb[2], dcb[3]));
        __stcs(reinterpret_cast<float4*>(&out[o + 2 * stride]),
               make_float4(dcr[0], dcr[1], dcr[2], dcr[3]));
    }
}

extern "C" void kernel_launch(void* const* d_in, const int* in_sizes, int n_in,
                              void* d_out, int out_size) {
    const float* left  = (const float*)d_in[0];
    const float* right = (const float*)d_in[1];
    float* out = (float*)d_out;
    // maxdisp lives in device memory (d_in[2]); derive it host-side from out_size.
    int maxdisp = out_size / (3 * HW);   // = 128 for the bench shape

    dim3 pgrid(W / TX, H / TY, 2);       // 15 x 40 x 2
    prep_kernel<<<pgrid, 256>>>(left, right);

    // Volume kernel launched with PDL so its launch/prologue overlaps prep's tail.
    cudaLaunchConfig_t cfg = {};
    cfg.gridDim  = dim3(H, (maxdisp + DPB - 1) / DPB);  // 320 x 16, y fastest
    cfg.blockDim = dim3(256, 1, 1);
    cfg.dynamicSmemBytes = 0;
    cfg.stream = 0;
    cudaLaunchAttribute attr[1];
    attr[0].id = cudaLaunchAttributeProgrammaticStreamSerialization;
    attr[0].val.programmaticStreamSerializationAllowed = 1;
    cfg.attrs = attr;
    cfg.numAttrs = 1;
    cudaLaunchKernelEx(&cfg, volume_kernel, out, maxdisp);
}

// round 15
// speedup vs baseline: 1.1656x; 1.0264x over previous
#include <cuda_runtime.h>
#include <cstdint>

#define H 320
#define W 960
#define HW (H * W)
#define PAD 128   // slack so left-window vector loads can't run past the array

// Fused prep tile config
#define TX 64
#define TY 8
#define SX (TX + 4)
#define SY (TY + 4)

// Disparities per volume block (multiple of 4 for aligned left loads)
#define DPB 8

// Scratch (allocation-free: __device__ globals). Y plane never hits global.
__device__ float g_cbL[HW + PAD], g_cbR[HW + PAD];
__device__ float g_crL[HW + PAD], g_crR[HW + PAD];
__device__ unsigned g_cL[HW + PAD], g_cR[HW + PAD];

// Fused YCbCr + census. One block per 64x8 tile per image (blockIdx.z).
__global__ __launch_bounds__(256) void prep_kernel(const float* __restrict__ left,
                                                   const float* __restrict__ right) {
    int img = blockIdx.z;
    const float* src = img ? right : left;
    float* cb    = img ? g_cbR : g_cbL;
    float* cr    = img ? g_crR : g_crL;
    unsigned* C  = img ? g_cR  : g_cL;

    __shared__ float sY[SY][SX];
    int tx0 = blockIdx.x * TX, ty0 = blockIdx.y * TY;

    // Phase 1: compute Y for tile+halo into smem; write cb/cr for interior.
    for (int idx = threadIdx.x; idx < SX * SY; idx += 256) {
        int sy = idx / SX, sx = idx - sy * SX;
        int gx = tx0 + sx - 2, gy = ty0 + sy - 2;
        float yv = 0.0f;
        if (gx >= 0 && gx < W && gy >= 0 && gy < H) {
            int p = gy * W + gx;
            float r = src[p], g = src[HW + p], b = src[2 * HW + p];
            yv = 0.299f * r + 0.587f * g + 0.114f * b;
            if (sx >= 2 && sx < SX - 2 && sy >= 2 && sy < SY - 2) {
                cb[p] = (b - yv) * 0.564f + 0.5f;
                cr[p] = (r - yv) * 0.713f + 0.5f;
            }
        }
        sY[sy][sx] = yv;
    }
    __syncthreads();

    // Phase 2: census from smem.
    int px = threadIdx.x % TX;
    for (int py = threadIdx.x / TX; py < TY; py += 256 / TX) {
        int gx = tx0 + px, gy = ty0 + py;
        unsigned cen = 0u;
        if (gx >= 2 && gx < W - 2 && gy >= 2 && gy < H - 2) {
            float c = sY[py + 2][px + 2];
            #pragma unroll
            for (int v = 0; v < 5; v++) {
                #pragma unroll
                for (int u = 0; u < 5; u++) {
                    if (v == 1 && u == 1) continue;  // reference skips (1,1), NOT the center
                    cen = (cen << 1) | (sY[py + v][px + u] >= c ? 1u : 0u);
                }
            }
        }
        C[gy * W + gx] = cen;
    }

    // PDL: allow the dependent volume kernel to begin launching.
    asm volatile("griddepcontrol.launch_dependents;");
}

// Grid: (y=H fastest, d-group, channel). Concurrently-resident blocks all
// write ONE output plane in consecutive y rows -> a single sequential DRAM
// store stream (max page/burst locality; the 3-interleaved-stream version
// measured DRAM=73.6%). Per block: lanes 0..239 produce 4 consecutive x for
// ONE channel across DPB disparities. Left window = 3 aligned vector loads
// (d0 % 4 == 0); per-disparity selection is register shuffling.
// Out-of-range lanes read neighbor-row garbage (masked on output; arrays padded).
__global__ __launch_bounds__(256) void volume_kernel(float* __restrict__ out,
                                                     int maxdisp) {
    int y  = blockIdx.x;
    int d0 = blockIdx.y * DPB;
    int ch = blockIdx.z;                 // 0=hamming, 1=|dCb|, 2=|dCr|
    int lane = threadIdx.x;
    int x = lane * 4;
    int rbase = y * W + x;
    int lb = rbase + d0;
    int rem = W - x - d0;                // element (dd, j) valid iff dd + j < rem
    size_t obase = ((size_t)(ch * maxdisp + d0) * H + y) * W + x;

    // PDL: block until prep_kernel has fully completed (all its stores visible).
    asm volatile("griddepcontrol.wait;");

    if (lane >= W / 4) return;

    if (ch == 0) {
        // Census hamming channel
        uint4 c4 = *reinterpret_cast<const uint4*>(&g_cR[rbase]);
        unsigned cR[4] = {c4.x, c4.y, c4.z, c4.w};
        unsigned cl[DPB + 4];
        #pragma unroll
        for (int g = 0; g < (DPB + 4) / 4; g++) {
            uint4 cv = *reinterpret_cast<const uint4*>(&g_cL[lb + 4 * g]);
            cl[4 * g + 0] = cv.x; cl[4 * g + 1] = cv.y; cl[4 * g + 2] = cv.z; cl[4 * g + 3] = cv.w;
        }
        #pragma unroll
        for (int dd = 0; dd < DPB; dd++) {
            float v[4];
            #pragma unroll
            for (int j = 0; j < 4; j++)
                v[j] = ((dd + j) < rem) ? (float)__popc(cl[dd + j] ^ cR[j]) : 0.0f;
            __stcs(reinterpret_cast<float4*>(&out[obase + (size_t)dd * HW]),
                   make_float4(v[0], v[1], v[2], v[3]));
        }
    } else {
        // Chroma abs-diff channel
        const float* L = (ch == 1) ? g_cbL : g_crL;
        const float* R = (ch == 1) ? g_cbR : g_crR;
        float4 r4 = *reinterpret_cast<const float4*>(&R[rbase]);
        float vR[4] = {r4.x, r4.y, r4.z, r4.w};
        float vl[DPB + 4];
        #pragma unroll
        for (int g = 0; g < (DPB + 4) / 4; g++) {
            float4 lv = *reinterpret_cast<const float4*>(&L[lb + 4 * g]);
            vl[4 * g + 0] = lv.x; vl[4 * g + 1] = lv.y; vl[4 * g + 2] = lv.z; vl[4 * g + 3] = lv.w;
        }
        #pragma unroll
        for (int dd = 0; dd < DPB; dd++) {
            float v[4];
            #pragma unroll
            for (int j = 0; j < 4; j++)
                v[j] = ((dd + j) < rem) ? fabsf(vl[dd + j] - vR[j]) : 0.0f;
            __stcs(reinterpret_cast<float4*>(&out[obase + (size_t)dd * HW]),
                   make_float4(v[0], v[1], v[2], v[3]));
        }
    }
}

extern "C" void kernel_launch(void* const* d_in, const int* in_sizes, int n_in,
                              void* d_out, int out_size) {
    const float* left  = (const float*)d_in[0];
    const float* right = (const float*)d_in[1];
    float* out = (float*)d_out;
    // maxdisp lives in device memory (d_in[2]); derive it host-side from out_size.
    int maxdisp = out_size / (3 * HW);   // = 128 for the bench shape

    dim3 pgrid(W / TX, H / TY, 2);       // 15 x 40 x 2
    prep_kernel<<<pgrid, 256>>>(left, right);

    // Volume kernel launched with PDL so its launch/prologue overlaps prep's tail.
    cudaLaunchConfig_t cfg = {};
    cfg.gridDim  = dim3(H, (maxdisp + DPB - 1) / DPB, 3);  // 320 x 16 x 3, y fastest
    cfg.blockDim = dim3(256, 1, 1);
    cfg.dynamicSmemBytes = 0;
    cfg.stream = 0;
    cudaLaunchAttribute attr[1];
    attr[0].id = cudaLaunchAttributeProgrammaticStreamSerialization;
    attr[0].val.programmaticStreamSerializationAllowed = 1;
    cfg.attrs = attr;
    cfg.numAttrs = 1;
    cudaLaunchKernelEx(&cfg, volume_kernel, out, maxdisp);
}